// round 6
// baseline (speedup 1.0000x reference)
#include <cuda_runtime.h>
#include <cstdint>

// ---------------------------------------------------------------------------
// QuantumLayer, single fused kernel, per-row device barrier, fully-resident
// grid: 1024 blocks x 256 thr @ <=32 regs (launch_bounds 256,8) -> 8 blocks/SM
// -> 1184 resident slots >= 1024 blocks: whole grid co-resident, barrier is
// deadlock-free by construction. m2 round-trips through L2 (write, barrier,
// __ldcg read) instead of living in registers, freeing regs for occupancy.
// ---------------------------------------------------------------------------

__device__ float    g_partials[1024];
__device__ uint32_t g_rowcnt[256];   // monotonic across graph replays

// ----------------------------- complex helpers -----------------------------
__device__ __forceinline__ float2 cmul(float2 a, float2 b) {
    return make_float2(a.x * b.x - a.y * b.y, a.x * b.y + a.y * b.x);
}
__device__ __forceinline__ float2 cadd(float2 a, float2 b) {
    return make_float2(a.x + b.x, a.y + b.y);
}

struct C2x2 { float2 m00, m01, m10, m11; };

__device__ __forceinline__ C2x2 mmul(const C2x2& A, const C2x2& B) {  // A*B
    C2x2 R;
    R.m00 = cadd(cmul(A.m00, B.m00), cmul(A.m01, B.m10));
    R.m01 = cadd(cmul(A.m00, B.m01), cmul(A.m01, B.m11));
    R.m10 = cadd(cmul(A.m10, B.m00), cmul(A.m11, B.m10));
    R.m11 = cadd(cmul(A.m10, B.m01), cmul(A.m11, B.m11));
    return R;
}

__device__ __forceinline__ float2 shf2(float2 v, int off) {
    return make_float2(__shfl_down_sync(0xFFFFFFFFu, v.x, off),
                       __shfl_down_sync(0xFFFFFFFFu, v.y, off));
}
__device__ __forceinline__ C2x2 shfm(const C2x2& P, int off) {
    C2x2 Q;
    Q.m00 = shf2(P.m00, off); Q.m01 = shf2(P.m01, off);
    Q.m10 = shf2(P.m10, off); Q.m11 = shf2(P.m11, off);
    return Q;
}

// ----------------------------- threefry-2x32 -------------------------------
__device__ __forceinline__ uint2 threefry2x32(uint32_t k0, uint32_t k1,
                                              uint32_t x0, uint32_t x1) {
    uint32_t ks2 = 0x1BD11BDAu ^ k0 ^ k1;
#define TF_R(r) { x0 += x1; x1 = __funnelshift_l(x1, x1, (r)); x1 ^= x0; }
    x0 += k0;  x1 += k1;
    TF_R(13) TF_R(15) TF_R(26) TF_R(6)
    x0 += k1;  x1 += ks2 + 1u;
    TF_R(17) TF_R(29) TF_R(16) TF_R(24)
    x0 += ks2; x1 += k0 + 2u;
    TF_R(13) TF_R(15) TF_R(26) TF_R(6)
    x0 += k0;  x1 += k1 + 3u;
    TF_R(17) TF_R(29) TF_R(16) TF_R(24)
    x0 += k1;  x1 += ks2 + 4u;
    TF_R(13) TF_R(15) TF_R(26) TF_R(6)
    x0 += ks2; x1 += k0 + 5u;
#undef TF_R
    return make_uint2(x0, x1);
}

// ------------------- XLA erf_inv (f32), fast log variant -------------------
__device__ __forceinline__ float xla_erfinv_fast(float x) {
    float w = -__logf(fmaf(x, -x, 1.0f));
    float p;
    if (w < 5.0f) {
        w -= 2.5f;
        p = 2.81022636e-08f;
        p = fmaf(p, w, 3.43273939e-07f);
        p = fmaf(p, w, -3.5233877e-06f);
        p = fmaf(p, w, -4.39150654e-06f);
        p = fmaf(p, w, 0.00021858087f);
        p = fmaf(p, w, -0.00125372503f);
        p = fmaf(p, w, -0.00417768164f);
        p = fmaf(p, w, 0.246640727f);
        p = fmaf(p, w, 1.50140941f);
    } else {
        w = sqrtf(w) - 3.0f;
        p = -0.000200214257f;
        p = fmaf(p, w, 0.000100950558f);
        p = fmaf(p, w, 0.00134934322f);
        p = fmaf(p, w, -0.00367342844f);
        p = fmaf(p, w, 0.00573950773f);
        p = fmaf(p, w, -0.0076224613f);
        p = fmaf(p, w, 0.00943887047f);
        p = fmaf(p, w, 1.00167406f);
        p = fmaf(p, w, 2.83297682f);
    }
    return p * x;
}

// one noise element, exact JAX uniform semantics
__device__ __forceinline__ float noise_val(uint32_t k0, uint32_t k1, uint32_t j) {
    const float LO = -0.99999994039535522461f;   // nextafter(-1, 0)
    uint2 b = threefry2x32(k0, k1, 0u, j);
    uint32_t bits = b.x ^ b.y;
    float f = __uint_as_float((bits >> 9) | 0x3f800000u) - 1.0f;  // [0,1) exact
    float u = fmaxf(LO, fmaf(f, 2.0f, LO));
    return xla_erfinv_fast(u) * 0.01f;
}

// ---------------------------------------------------------------------------
__global__ __launch_bounds__(256, 8) void k_fused(
    const float* __restrict__ rx, const float* __restrict__ ry,
    const float* __restrict__ rz, float* __restrict__ out,
    uint32_t kre0, uint32_t kre1, uint32_t kim0, uint32_t kim1) {

    const int t   = threadIdx.x;
    const int bid = blockIdx.x;
    const int row = bid >> 2;
    const int seg = bid & 3;

    // ---- warp 0 of seg==0 blocks: ordered product of 78 gate matrices ----
    float2 amp = {0.f, 0.f};
    if (seg == 0 && t < 32) {
        const int lane = t;
        const int lo = (lane * 78) >> 5;
        const int hi = ((lane + 1) * 78) >> 5;
        C2x2 P;
        P.m00 = {1.f, 0.f}; P.m01 = {0.f, 0.f};
        P.m10 = {0.f, 0.f}; P.m11 = {1.f, 0.f};
        for (int g = lo; g < hi; ++g) {
            float a; int axis;
            if (g < 26)      { a = __ldg(rx + g);      axis = 0; }
            else if (g < 52) { a = __ldg(ry + g - 26); axis = 1; }
            else             { a = __ldg(rz + g - 52); axis = 2; }
            float s, c;
            sincosf(0.5f * a, &s, &c);
            float2 e00, e01, e10, e11;
            if (axis == 0) {        // rx
                e00 = {c, 0.f}; e01 = {0.f, -s}; e10 = {0.f, -s}; e11 = {c, 0.f};
            } else if (axis == 1) { // ry
                e00 = {c, 0.f}; e01 = {-s, 0.f}; e10 = {s, 0.f};  e11 = {c, 0.f};
            } else {                // rz
                e00 = {c, -s};  e01 = {0.f, 0.f}; e10 = {0.f, 0.f}; e11 = {c, s};
            }
            // fold the reference's in-place aliasing bug
            C2x2 E;
            E.m00 = e00;
            E.m01 = e01;
            E.m10 = cmul(e10, e00);
            E.m11 = cadd(cmul(e10, e01), e11);
            P = mmul(E, P);
        }
        #pragma unroll
        for (int off = 1; off < 32; off <<= 1) {
            C2x2 Q = shfm(P, off);
            if ((lane & (2 * off - 1)) == 0) P = mmul(Q, P);
        }
        float2 a0, a1;
        a0.x = __shfl_sync(0xFFFFFFFFu, P.m00.x, 0);
        a0.y = __shfl_sync(0xFFFFFFFFu, P.m00.y, 0);
        a1.x = __shfl_sync(0xFFFFFFFFu, P.m10.x, 0);
        a1.y = __shfl_sync(0xFFFFFFFFu, P.m10.y, 0);
        if (lane == 0) amp = a0;
        if (lane == 1) amp = a1;
    }

    const uint32_t base = (uint32_t)(row * 8192 + seg * 2048 + t);
    float local = 0.0f;

    // k = 0 peeled so amp registers die early; m2 goes to gmem (L2-hot)
    {
        float re = noise_val(kre0, kre1, base);
        float im = noise_val(kim0, kim1, base);
        if (seg == 0 && t < 2) { re += amp.x; im += amp.y; }
        float m2 = fmaf(re, re, im * im);
        local += m2;
        out[base] = m2;
    }
#pragma unroll
    for (int k = 1; k < 8; k++) {
        float re = noise_val(kre0, kre1, base + k * 256);
        float im = noise_val(kim0, kim1, base + k * 256);
        float m2 = fmaf(re, re, im * im);
        local += m2;
        out[base + k * 256] = m2;
    }

    // ---- block reduction (8 warps) ----
    __shared__ float wsum[8];
    __shared__ float rinv_s;
#pragma unroll
    for (int o = 16; o; o >>= 1) local += __shfl_xor_sync(0xFFFFFFFFu, local, o);
    if ((t & 31) == 0) wsum[t >> 5] = local;
    __syncthreads();

    // ---- per-row device barrier + rinv (thread 0 only) ----
    if (t == 0) {
        float v = wsum[0] + wsum[1] + wsum[2] + wsum[3]
                + wsum[4] + wsum[5] + wsum[6] + wsum[7];
        g_partials[bid] = v;
        __threadfence();
        uint32_t old = atomicAdd(&g_rowcnt[row], 1u);
        uint32_t target = ((old >> 2) + 1u) << 2;   // 4*(epoch+1)
        unsigned ns = 64;
        while ((int)(atomicAdd(&g_rowcnt[row], 0u) - target) < 0) {
            __nanosleep(ns);
            if (ns < 1024) ns <<= 1;
        }
        __threadfence();
        float s = __ldcg(&g_partials[row * 4 + 0])
                + __ldcg(&g_partials[row * 4 + 1])
                + __ldcg(&g_partials[row * 4 + 2])
                + __ldcg(&g_partials[row * 4 + 3]);
        rinv_s = 1.0f / sqrtf(s);
    }
    __syncthreads();
    const float rinv = rinv_s;

    // ---- read m2 back (L2-hot), finalize, single output write ----
#pragma unroll
    for (int k = 0; k < 8; k++) {
        float m2 = __ldcg(&out[base + k * 256]);
        out[base + k * 256] = sqrtf(m2) * rinv;
    }
}

// ------------------------- host-side threefry ------------------------------
static inline uint32_t h_rotl(uint32_t x, int r) { return (x << r) | (x >> (32 - r)); }
static void h_threefry(uint32_t k0, uint32_t k1, uint32_t x0, uint32_t x1,
                       uint32_t* o0, uint32_t* o1) {
    uint32_t ks2 = 0x1BD11BDAu ^ k0 ^ k1;
#define HTF(r) { x0 += x1; x1 = h_rotl(x1, (r)); x1 ^= x0; }
    x0 += k0;  x1 += k1;
    HTF(13) HTF(15) HTF(26) HTF(6)
    x0 += k1;  x1 += ks2 + 1u;
    HTF(17) HTF(29) HTF(16) HTF(24)
    x0 += ks2; x1 += k0 + 2u;
    HTF(13) HTF(15) HTF(26) HTF(6)
    x0 += k0;  x1 += k1 + 3u;
    HTF(17) HTF(29) HTF(16) HTF(24)
    x0 += k1;  x1 += ks2 + 4u;
    HTF(13) HTF(15) HTF(26) HTF(6)
    x0 += ks2; x1 += k0 + 5u;
#undef HTF
    *o0 = x0; *o1 = x1;
}

// ---------------------------------------------------------------------------
extern "C" void kernel_launch(void* const* d_in, const int* in_sizes, int n_in,
                              void* d_out, int out_size) {
    // metadata order: x (unused), rx_params, ry_params, rz_params
    const float* rx = (const float*)d_in[1];
    const float* ry = (const float*)d_in[2];
    const float* rz = (const float*)d_in[3];
    float* out = (float*)d_out;

    uint32_t kre0, kre1, kim0, kim1;
    h_threefry(0u, 42u, 0u, 0u, &kre0, &kre1);
    h_threefry(0u, 42u, 0u, 1u, &kim0, &kim1);

    k_fused<<<1024, 256>>>(rx, ry, rz, out, kre0, kre1, kim0, kim1);
}

// round 7
// speedup vs baseline: 1.0675x; 1.0675x over previous
#include <cuda_runtime.h>
#include <cstdint>

// ---------------------------------------------------------------------------
// QuantumLayer. Two kernels:
//  k_noise: grid 2048 x 128thr, 8 elems/thread, 4 independent threefry chains
//           per iteration (2 elements x re/im) for ALU-pipe ILP. Writes m2 and
//           per-block partial sums.
//  k_scale: grid 2048 x 256thr, rinv per row from 8 partials (warp reduce),
//           out = sqrt(m2) * rinv.  8MB output is L2-resident between kernels.
// ---------------------------------------------------------------------------

__device__ float g_partials[2048];

// ----------------------------- complex helpers -----------------------------
__device__ __forceinline__ float2 cmul(float2 a, float2 b) {
    return make_float2(a.x * b.x - a.y * b.y, a.x * b.y + a.y * b.x);
}
__device__ __forceinline__ float2 cadd(float2 a, float2 b) {
    return make_float2(a.x + b.x, a.y + b.y);
}

struct C2x2 { float2 m00, m01, m10, m11; };

__device__ __forceinline__ C2x2 mmul(const C2x2& A, const C2x2& B) {  // A*B
    C2x2 R;
    R.m00 = cadd(cmul(A.m00, B.m00), cmul(A.m01, B.m10));
    R.m01 = cadd(cmul(A.m00, B.m01), cmul(A.m01, B.m11));
    R.m10 = cadd(cmul(A.m10, B.m00), cmul(A.m11, B.m10));
    R.m11 = cadd(cmul(A.m10, B.m01), cmul(A.m11, B.m11));
    return R;
}

__device__ __forceinline__ float2 shf2(float2 v, int off) {
    return make_float2(__shfl_down_sync(0xFFFFFFFFu, v.x, off),
                       __shfl_down_sync(0xFFFFFFFFu, v.y, off));
}
__device__ __forceinline__ C2x2 shfm(const C2x2& P, int off) {
    C2x2 Q;
    Q.m00 = shf2(P.m00, off); Q.m01 = shf2(P.m01, off);
    Q.m10 = shf2(P.m10, off); Q.m11 = shf2(P.m11, off);
    return Q;
}

// ----------------------------- threefry-2x32 -------------------------------
__device__ __forceinline__ uint2 threefry2x32(uint32_t k0, uint32_t k1,
                                              uint32_t x0, uint32_t x1) {
    uint32_t ks2 = 0x1BD11BDAu ^ k0 ^ k1;
#define TF_R(r) { x0 += x1; x1 = __funnelshift_l(x1, x1, (r)); x1 ^= x0; }
    x0 += k0;  x1 += k1;
    TF_R(13) TF_R(15) TF_R(26) TF_R(6)
    x0 += k1;  x1 += ks2 + 1u;
    TF_R(17) TF_R(29) TF_R(16) TF_R(24)
    x0 += ks2; x1 += k0 + 2u;
    TF_R(13) TF_R(15) TF_R(26) TF_R(6)
    x0 += k0;  x1 += k1 + 3u;
    TF_R(17) TF_R(29) TF_R(16) TF_R(24)
    x0 += k1;  x1 += ks2 + 4u;
    TF_R(13) TF_R(15) TF_R(26) TF_R(6)
    x0 += ks2; x1 += k0 + 5u;
#undef TF_R
    return make_uint2(x0, x1);
}

// two counters (ja, jb), same key: 4-op rounds interleave across both chains.
__device__ __forceinline__ uint2 threefry_pair(uint32_t k0, uint32_t k1,
                                               uint32_t ja, uint32_t jb) {
    uint32_t ks2 = 0x1BD11BDAu ^ k0 ^ k1;
    uint32_t a0 = k0, a1 = ja + k1;
    uint32_t b0 = k0, b1 = jb + k1;
#define TF2(r) { a0 += a1; b0 += b1; \
                 a1 = __funnelshift_l(a1, a1, (r)); b1 = __funnelshift_l(b1, b1, (r)); \
                 a1 ^= a0; b1 ^= b0; }
    TF2(13) TF2(15) TF2(26) TF2(6)
    a0 += k1;  b0 += k1;  a1 += ks2 + 1u; b1 += ks2 + 1u;
    TF2(17) TF2(29) TF2(16) TF2(24)
    a0 += ks2; b0 += ks2; a1 += k0 + 2u;  b1 += k0 + 2u;
    TF2(13) TF2(15) TF2(26) TF2(6)
    a0 += k0;  b0 += k0;  a1 += k1 + 3u;  b1 += k1 + 3u;
    TF2(17) TF2(29) TF2(16) TF2(24)
    a0 += k1;  b0 += k1;  a1 += ks2 + 4u; b1 += ks2 + 4u;
    TF2(13) TF2(15) TF2(26) TF2(6)
    a0 += ks2; b0 += ks2; a1 += k0 + 5u;  b1 += k0 + 5u;
#undef TF2
    return make_uint2(a0 ^ a1, b0 ^ b1);   // lane0 ^ lane1 per counter
}

// ------------------- XLA erf_inv (f32), fast log variant -------------------
__device__ __forceinline__ float xla_erfinv_fast(float x) {
    float w = -__logf(fmaf(x, -x, 1.0f));
    float p;
    if (w < 5.0f) {
        w -= 2.5f;
        p = 2.81022636e-08f;
        p = fmaf(p, w, 3.43273939e-07f);
        p = fmaf(p, w, -3.5233877e-06f);
        p = fmaf(p, w, -4.39150654e-06f);
        p = fmaf(p, w, 0.00021858087f);
        p = fmaf(p, w, -0.00125372503f);
        p = fmaf(p, w, -0.00417768164f);
        p = fmaf(p, w, 0.246640727f);
        p = fmaf(p, w, 1.50140941f);
    } else {
        w = sqrtf(w) - 3.0f;
        p = -0.000200214257f;
        p = fmaf(p, w, 0.000100950558f);
        p = fmaf(p, w, 0.00134934322f);
        p = fmaf(p, w, -0.00367342844f);
        p = fmaf(p, w, 0.00573950773f);
        p = fmaf(p, w, -0.0076224613f);
        p = fmaf(p, w, 0.00943887047f);
        p = fmaf(p, w, 1.00167406f);
        p = fmaf(p, w, 2.83297682f);
    }
    return p * x;
}

__device__ __forceinline__ float bits_to_noise(uint32_t bits) {
    const float LO = -0.99999994039535522461f;   // nextafter(-1, 0)
    float f = __uint_as_float((bits >> 9) | 0x3f800000u) - 1.0f;  // [0,1) exact
    float u = fmaxf(LO, fmaf(f, 2.0f, LO));
    return xla_erfinv_fast(u) * 0.01f;
}

// ---------------------------------------------------------------------------
// K1: noise + m2.  grid = 2048 (256 rows x 8 segs), block = 128, 8 elem/thr.
// ---------------------------------------------------------------------------
__global__ void k_noise(
    const float* __restrict__ rx, const float* __restrict__ ry,
    const float* __restrict__ rz, float* __restrict__ out,
    uint32_t kre0, uint32_t kre1, uint32_t kim0, uint32_t kim1) {

    const int t   = threadIdx.x;
    const int bid = blockIdx.x;
    const int row = bid >> 3;
    const int seg = bid & 7;

    // ---- warp 0 of seg==0 blocks: ordered product of 78 gate matrices ----
    float2 amp = {0.f, 0.f};
    if (seg == 0 && t < 32) {
        const int lane = t;
        const int lo = (lane * 78) >> 5;
        const int hi = ((lane + 1) * 78) >> 5;
        C2x2 P;
        P.m00 = {1.f, 0.f}; P.m01 = {0.f, 0.f};
        P.m10 = {0.f, 0.f}; P.m11 = {1.f, 0.f};
        for (int g = lo; g < hi; ++g) {
            float a; int axis;
            if (g < 26)      { a = __ldg(rx + g);      axis = 0; }
            else if (g < 52) { a = __ldg(ry + g - 26); axis = 1; }
            else             { a = __ldg(rz + g - 52); axis = 2; }
            float s, c;
            sincosf(0.5f * a, &s, &c);
            float2 e00, e01, e10, e11;
            if (axis == 0) {        // rx
                e00 = {c, 0.f}; e01 = {0.f, -s}; e10 = {0.f, -s}; e11 = {c, 0.f};
            } else if (axis == 1) { // ry
                e00 = {c, 0.f}; e01 = {-s, 0.f}; e10 = {s, 0.f};  e11 = {c, 0.f};
            } else {                // rz
                e00 = {c, -s};  e01 = {0.f, 0.f}; e10 = {0.f, 0.f}; e11 = {c, s};
            }
            // fold the reference's in-place aliasing bug
            C2x2 E;
            E.m00 = e00;
            E.m01 = e01;
            E.m10 = cmul(e10, e00);
            E.m11 = cadd(cmul(e10, e01), e11);
            P = mmul(E, P);
        }
        #pragma unroll
        for (int off = 1; off < 32; off <<= 1) {
            C2x2 Q = shfm(P, off);
            if ((lane & (2 * off - 1)) == 0) P = mmul(Q, P);
        }
        float2 a0, a1;
        a0.x = __shfl_sync(0xFFFFFFFFu, P.m00.x, 0);
        a0.y = __shfl_sync(0xFFFFFFFFu, P.m00.y, 0);
        a1.x = __shfl_sync(0xFFFFFFFFu, P.m10.x, 0);
        a1.y = __shfl_sync(0xFFFFFFFFu, P.m10.y, 0);
        if (lane == 0) amp = a0;
        if (lane == 1) amp = a1;
    }

    const uint32_t base = (uint32_t)(row * 8192 + seg * 1024 + t);
    float local = 0.0f;

    // k = 0 pair peeled: amp add lives only here
    {
        const uint32_t ja = base, jb = base + 128;
        uint2 br = threefry_pair(kre0, kre1, ja, jb);
        uint2 bi = threefry_pair(kim0, kim1, ja, jb);
        float rea = bits_to_noise(br.x), reb = bits_to_noise(br.y);
        float ima = bits_to_noise(bi.x), imb = bits_to_noise(bi.y);
        if (seg == 0 && t < 2) { rea += amp.x; ima += amp.y; }
        float m2a = fmaf(rea, rea, ima * ima);
        float m2b = fmaf(reb, reb, imb * imb);
        local += m2a + m2b;
        out[ja] = m2a;
        out[jb] = m2b;
    }
#pragma unroll
    for (int k = 1; k < 4; k++) {
        const uint32_t ja = base + k * 256, jb = ja + 128;
        uint2 br = threefry_pair(kre0, kre1, ja, jb);
        uint2 bi = threefry_pair(kim0, kim1, ja, jb);
        float rea = bits_to_noise(br.x), reb = bits_to_noise(br.y);
        float ima = bits_to_noise(bi.x), imb = bits_to_noise(bi.y);
        float m2a = fmaf(rea, rea, ima * ima);
        float m2b = fmaf(reb, reb, imb * imb);
        local += m2a + m2b;
        out[ja] = m2a;
        out[jb] = m2b;
    }

    // ---- block reduction (4 warps) ----
    __shared__ float wsum[4];
#pragma unroll
    for (int o = 16; o; o >>= 1) local += __shfl_xor_sync(0xFFFFFFFFu, local, o);
    if ((t & 31) == 0) wsum[t >> 5] = local;
    __syncthreads();
    if (t == 0) {
        g_partials[bid] = wsum[0] + wsum[1] + wsum[2] + wsum[3];
    }
}

// ---------------------------------------------------------------------------
// K2: rinv per row (8 partials, 8-lane reduce), out = sqrt(m2) * rinv.
// grid = 2048, block = 256, one float4 per thread. All traffic L2-hot.
// ---------------------------------------------------------------------------
__global__ __launch_bounds__(256) void k_scale(float* __restrict__ out) {
    const int bid = blockIdx.x;
    const int t   = threadIdx.x;
    const int row = bid >> 3;

    __shared__ float rinv_s;
    if (t < 32) {
        float v = (t < 8) ? __ldcg(&g_partials[row * 8 + t]) : 0.0f;
        v += __shfl_xor_sync(0xFFFFFFFFu, v, 4);
        v += __shfl_xor_sync(0xFFFFFFFFu, v, 2);
        v += __shfl_xor_sync(0xFFFFFFFFu, v, 1);
        if (t == 0) rinv_s = rsqrtf(v);
    }
    __syncthreads();
    const float rinv = rinv_s;

    float4* o4 = reinterpret_cast<float4*>(out);
    const int f = bid * 256 + t;
    float4 v = o4[f];
    v.x = sqrtf(v.x) * rinv;
    v.y = sqrtf(v.y) * rinv;
    v.z = sqrtf(v.z) * rinv;
    v.w = sqrtf(v.w) * rinv;
    o4[f] = v;
}

// ------------------------- host-side threefry ------------------------------
static inline uint32_t h_rotl(uint32_t x, int r) { return (x << r) | (x >> (32 - r)); }
static void h_threefry(uint32_t k0, uint32_t k1, uint32_t x0, uint32_t x1,
                       uint32_t* o0, uint32_t* o1) {
    uint32_t ks2 = 0x1BD11BDAu ^ k0 ^ k1;
#define HTF(r) { x0 += x1; x1 = h_rotl(x1, (r)); x1 ^= x0; }
    x0 += k0;  x1 += k1;
    HTF(13) HTF(15) HTF(26) HTF(6)
    x0 += k1;  x1 += ks2 + 1u;
    HTF(17) HTF(29) HTF(16) HTF(24)
    x0 += ks2; x1 += k0 + 2u;
    HTF(13) HTF(15) HTF(26) HTF(6)
    x0 += k0;  x1 += k1 + 3u;
    HTF(17) HTF(29) HTF(16) HTF(24)
    x0 += k1;  x1 += ks2 + 4u;
    HTF(13) HTF(15) HTF(26) HTF(6)
    x0 += ks2; x1 += k0 + 5u;
#undef HTF
    *o0 = x0; *o1 = x1;
}

// ---------------------------------------------------------------------------
extern "C" void kernel_launch(void* const* d_in, const int* in_sizes, int n_in,
                              void* d_out, int out_size) {
    // metadata order: x (unused), rx_params, ry_params, rz_params
    const float* rx = (const float*)d_in[1];
    const float* ry = (const float*)d_in[2];
    const float* rz = (const float*)d_in[3];
    float* out = (float*)d_out;

    uint32_t kre0, kre1, kim0, kim1;
    h_threefry(0u, 42u, 0u, 0u, &kre0, &kre1);
    h_threefry(0u, 42u, 0u, 1u, &kim0, &kim1);

    k_noise<<<2048, 128>>>(rx, ry, rz, out, kre0, kre1, kim0, kim1);
    k_scale<<<2048, 256>>>(out);
}